// round 15
// baseline (speedup 1.0000x reference)
#include <cuda_runtime.h>
#include <cuda_bf16.h>

#define NN 50000
#define NE 800000
#define NG 512
#define DN 64
#define DE 32
#define ET 64            // edges per block tile -> 12500 blocks

// Scratch (allocation-free: __device__ globals)
// ABd[node][128]: pairs {af[ch], as[ch]} for ch=0..63 (dst gather)
// ABs[node][128]: pairs {bf[ch], bs[ch]} for ch=0..63 (src gather)
__device__ float g_ABd[NN * 128];
__device__ float g_ABs[NN * 128];
__device__ float g_h1[NN * DN];
__device__ float g_h2[NN * DN];

// ---------------------------------------------------------------------------
// Node projection into paired gather layout (+ bias fold).
//   cb=0: af = h·Wf[0:64] + bf  -> ABd[.][2ch+0]
//   cb=1: bf = h·Wf[64:128]     -> ABs[.][2ch+0]
//   cb=2: as = h·Ws[0:64] + bs  -> ABd[.][2ch+1]
//   cb=3: bs = h·Ws[64:128]     -> ABs[.][2ch+1]
// ---------------------------------------------------------------------------
__global__ void __launch_bounds__(256) proj_kernel(
    const float* __restrict__ h, const float* __restrict__ Wf,
    const float* __restrict__ Ws, const float* __restrict__ bfv,
    const float* __restrict__ bsv, float* __restrict__ ABd,
    float* __restrict__ ABs)
{
    __shared__ float As[64][65];
    __shared__ float Bs[64][64];

    const int tid = threadIdx.x;
    const int node0 = blockIdx.x * 64;
    const int cb = blockIdx.y;

    const float* Wsrc = (cb < 2) ? Wf : Ws;
    const int rowoff = (cb & 1) ? 64 : 0;

#pragma unroll
    for (int t = 0; t < 16; t++) {
        int lin = t * 256 + tid;
        int k = lin >> 6, j = lin & 63;
        Bs[k][j] = Wsrc[(rowoff + k) * 64 + j];
    }
#pragma unroll
    for (int t = 0; t < 16; t++) {
        int lin = t * 256 + tid;
        int n = lin >> 6, k = lin & 63;
        int node = node0 + n;
        As[k][n] = (node < NN) ? h[node * 64 + k] : 0.0f;
    }
    __syncthreads();

    const int tx = tid & 15;
    const int ty = tid >> 4;
    float acc[4][4] = {};

#pragma unroll
    for (int k = 0; k < 64; k++) {
        float4 b4 = *(const float4*)&Bs[k][tx * 4];
        float a0 = As[k][ty * 4 + 0];
        float a1 = As[k][ty * 4 + 1];
        float a2 = As[k][ty * 4 + 2];
        float a3 = As[k][ty * 4 + 3];
        acc[0][0] += a0 * b4.x; acc[0][1] += a0 * b4.y; acc[0][2] += a0 * b4.z; acc[0][3] += a0 * b4.w;
        acc[1][0] += a1 * b4.x; acc[1][1] += a1 * b4.y; acc[1][2] += a1 * b4.z; acc[1][3] += a1 * b4.w;
        acc[2][0] += a2 * b4.x; acc[2][1] += a2 * b4.y; acc[2][2] += a2 * b4.z; acc[2][3] += a2 * b4.w;
        acc[3][0] += a3 * b4.x; acc[3][1] += a3 * b4.y; acc[3][2] += a3 * b4.z; acc[3][3] += a3 * b4.w;
    }

    float bias[4] = {0.f, 0.f, 0.f, 0.f};
    if (cb == 0) {
#pragma unroll
        for (int j = 0; j < 4; j++) bias[j] = bfv[tx * 4 + j];
    } else if (cb == 2) {
#pragma unroll
        for (int j = 0; j < 4; j++) bias[j] = bsv[tx * 4 + j];
    }

    float* outbase = (cb == 0 || cb == 2) ? ABd : ABs;
    const int sub = (cb >= 2) ? 1 : 0;   // slot within the {f,s} pair

#pragma unroll
    for (int i = 0; i < 4; i++) {
        int node = node0 + ty * 4 + i;
        if (node < NN) {
#pragma unroll
            for (int j = 0; j < 4; j++)
                outbase[(size_t)node * 128 + (tx * 4 + j) * 2 + sub] =
                    acc[i][j] + bias[j];
        }
    }
}

// ---------------------------------------------------------------------------
// Edge GEMM kernel, edge-pair layout: block = 64 edges x 64 channels, K=32.
// Thread (ch, eg) owns channel ch for 16 edges (8 edge-pairs). FFMA2 halves
// = 2 edges sharing one weight -> per k per warp: 2 B wavefronts + 4
// broadcast A wavefronts for 16 edges. 3 blocks/SM.
// ---------------------------------------------------------------------------
__device__ __forceinline__ float sigmoidf_(float x) {
    return 1.0f / (1.0f + __expf(-x));
}
__device__ __forceinline__ float softplusf_(float x) {
    float ax = fabsf(x);
    float em = __expf(-ax);
    return fmaxf(x, 0.0f) + __logf(1.0f + em);
}

__global__ void __launch_bounds__(256, 3) edge_gemm_kernel(
    const int* __restrict__ ei, const float* __restrict__ ea,
    const float* __restrict__ ABd, const float* __restrict__ ABs,
    const float* __restrict__ Wf, const float* __restrict__ Ws,
    float* __restrict__ hout)
{
    __shared__ float Asd[32][64];    // [k][edge], non-duplicated (8 KB)
    __shared__ float Bq[32][128];    // [k][2ch + {f,s}] (16 KB)
    __shared__ int   ssrc[ET], sdst[ET];

    const int tid = threadIdx.x;
    const int e0 = blockIdx.x * ET;

    // --- Stage edge indices ---
    if (tid < ET) {
        ssrc[tid] = ei[e0 + tid];
        sdst[tid] = ei[NE + e0 + tid];
    }

    // --- Stage ea: thread t -> edge t&63, k-quarter t>>6 (bank = edge: CF) ---
    {
        const int e = tid & 63;
        const int k0 = (tid >> 6) * 8;
        const float* src = ea + (size_t)(e0 + e) * 32 + k0;
        float4 v0 = *(const float4*)(src);
        float4 v1 = *(const float4*)(src + 4);
#pragma unroll
        for (int j = 0; j < 4; j++) Asd[k0 + j][e] = (&v0.x)[j];
#pragma unroll
        for (int j = 0; j < 4; j++) Asd[k0 + 4 + j][e] = (&v1.x)[j];
    }

    // --- Stage paired bottom weights: Bq[k][2ch+m] = W_m[128+k][ch] ---
#pragma unroll
    for (int q = 0; q < 16; q++) {
        int idx = q * 256 + tid;           // 4096 total
        int k = idx >> 7, col = idx & 127;
        int ch = col >> 1, m = col & 1;
        const float* W = m ? Ws : Wf;
        Bq[k][col] = W[(size_t)(128 + k) * 64 + ch];
    }
    __syncthreads();

    const int ch = tid & 63;   // channel 0..63
    const int eg = tid >> 6;   // edge group: edges eg*16 .. +15

    const unsigned abase = (unsigned)__cvta_generic_to_shared(&Asd[0][eg * 16]);
    const unsigned bbase = (unsigned)__cvta_generic_to_shared(&Bq[0][ch * 2]);

    unsigned long long accf[8] = {0}, accs[8] = {0};

#pragma unroll
    for (int k = 0; k < 32; k++) {
        float wfv, wsv;
        asm volatile("ld.shared.v2.f32 {%0, %1}, [%2];"
                     : "=f"(wfv), "=f"(wsv) : "r"(bbase + k * 512u));
        unsigned long long wfp, wsp;
        asm("mov.b64 %0, {%1, %1};" : "=l"(wfp) : "f"(wfv));
        asm("mov.b64 %0, {%1, %1};" : "=l"(wsp) : "f"(wsv));

        unsigned long long ap[8];   // pairs {e0,e1}..{e14,e15}
        asm volatile("ld.shared.v2.b64 {%0, %1}, [%2];"
                     : "=l"(ap[0]), "=l"(ap[1]) : "r"(abase + k * 256u));
        asm volatile("ld.shared.v2.b64 {%0, %1}, [%2];"
                     : "=l"(ap[2]), "=l"(ap[3]) : "r"(abase + k * 256u + 16u));
        asm volatile("ld.shared.v2.b64 {%0, %1}, [%2];"
                     : "=l"(ap[4]), "=l"(ap[5]) : "r"(abase + k * 256u + 32u));
        asm volatile("ld.shared.v2.b64 {%0, %1}, [%2];"
                     : "=l"(ap[6]), "=l"(ap[7]) : "r"(abase + k * 256u + 48u));
#pragma unroll
        for (int p = 0; p < 8; p++) {
            asm("fma.rn.f32x2 %0, %1, %2, %3;"
                : "=l"(accf[p]) : "l"(ap[p]), "l"(wfp), "l"(accf[p]));
            asm("fma.rn.f32x2 %0, %1, %2, %3;"
                : "=l"(accs[p]) : "l"(ap[p]), "l"(wsp), "l"(accs[p]));
        }
    }

    // --- Epilogue: 2 waves of 4 pairs (8 edges each) ---
#pragma unroll
    for (int w = 0; w < 2; w++) {
        float2 dd[8], ss[8];
        int dsts[8];
#pragma unroll
        for (int i = 0; i < 8; i++) {
            int el = eg * 16 + w * 8 + i;
            dsts[i] = sdst[el];
            int sr = ssrc[el];
            dd[i] = *(const float2*)(ABd + (size_t)dsts[i] * 128 + ch * 2);
            ss[i] = *(const float2*)(ABs + (size_t)sr * 128 + ch * 2);
        }
#pragma unroll
        for (int p = 0; p < 4; p++) {
            int j = w * 4 + p;      // accumulator pair index
            float ef0, ef1, es0, es1;
            asm("mov.b64 {%0, %1}, %2;" : "=f"(ef0), "=f"(ef1) : "l"(accf[j]));
            asm("mov.b64 {%0, %1}, %2;" : "=f"(es0), "=f"(es1) : "l"(accs[j]));
#pragma unroll
            for (int b = 0; b < 2; b++) {
                int i = 2 * p + b;
                float ef = b ? ef1 : ef0;
                float es = b ? es1 : es0;
                float pf = dd[i].x + ss[i].x + ef;
                float qv = dd[i].y + ss[i].y + es;
                float m = sigmoidf_(pf) * softplusf_(qv);
                float* outp = hout + (size_t)dsts[i] * 64 + ch;
                asm volatile("red.global.add.f32 [%0], %1;"
                             :: "l"(outp), "f"(m) : "memory");
            }
        }
    }
}

// ---------------------------------------------------------------------------
__global__ void init_out_kernel(float* __restrict__ out, const float* __restrict__ b_out)
{
    int t = threadIdx.x;
    if (t < NG) out[t] = b_out[0];
}

__global__ void __launch_bounds__(256) pool_kernel(
    const float* __restrict__ h2, const int* __restrict__ batch,
    const float* __restrict__ Wout, float* __restrict__ out)
{
    const int warp = blockIdx.x * (blockDim.x >> 5) + (threadIdx.x >> 5);
    const int lane = threadIdx.x & 31;
    if (warp >= NN) return;
    float2 v = *(const float2*)(h2 + (size_t)warp * 64 + 2 * lane);
    float s = v.x * Wout[2 * lane] + v.y * Wout[2 * lane + 1];
#pragma unroll
    for (int off = 16; off; off >>= 1)
        s += __shfl_down_sync(0xffffffffu, s, off);
    if (lane == 0) atomicAdd(&out[batch[warp]], s);
}

// ---------------------------------------------------------------------------
extern "C" void kernel_launch(void* const* d_in, const int* in_sizes, int n_in,
                              void* d_out, int out_size)
{
    const float* x     = (const float*)d_in[0];
    const int*   ei    = (const int*)d_in[1];
    const float* ea    = (const float*)d_in[2];
    const int*   batch = (const int*)d_in[3];
    const float* Wf1  = (const float*)d_in[4];
    const float* bf1  = (const float*)d_in[5];
    const float* Ws1  = (const float*)d_in[6];
    const float* bs1  = (const float*)d_in[7];
    const float* Wf2  = (const float*)d_in[8];
    const float* bf2  = (const float*)d_in[9];
    const float* Ws2  = (const float*)d_in[10];
    const float* bs2  = (const float*)d_in[11];
    const float* Wout = (const float*)d_in[12];
    const float* bout = (const float*)d_in[13];
    float* out = (float*)d_out;

    float *ABd, *ABs, *h1, *h2;
    cudaGetSymbolAddress((void**)&ABd, g_ABd);
    cudaGetSymbolAddress((void**)&ABs, g_ABs);
    cudaGetSymbolAddress((void**)&h1, g_h1);
    cudaGetSymbolAddress((void**)&h2, g_h2);

    const dim3 pgrid((NN + 63) / 64, 4);
    const int egrid = NE / ET;   // 12500

    // ---- Layer 1 ----
    proj_kernel<<<pgrid, 256>>>(x, Wf1, Ws1, bf1, bs1, ABd, ABs);
    cudaMemcpyAsync(h1, x, (size_t)NN * DN * sizeof(float),
                    cudaMemcpyDeviceToDevice);
    edge_gemm_kernel<<<egrid, 256>>>(ei, ea, ABd, ABs, Wf1, Ws1, h1);

    // ---- Layer 2 ----
    proj_kernel<<<pgrid, 256>>>(h1, Wf2, Ws2, bf2, bs2, ABd, ABs);
    cudaMemcpyAsync(h2, h1, (size_t)NN * DN * sizeof(float),
                    cudaMemcpyDeviceToDevice);
    edge_gemm_kernel<<<egrid, 256>>>(ei, ea, ABd, ABs, Wf2, Ws2, h2);

    // ---- Pool + readout ----
    init_out_kernel<<<1, 512>>>(out, bout);
    pool_kernel<<<NN / 8, 256>>>(h2, batch, Wout, out);
}

// round 16
// speedup vs baseline: 1.0290x; 1.0290x over previous
#include <cuda_runtime.h>
#include <cuda_bf16.h>

#define NN 50000
#define NE 800000
#define NG 512
#define DN 64
#define DE 32
#define ET 64            // edges per block tile -> 12500 blocks

// Scratch (allocation-free: __device__ globals)
// ABd[node][128]: pairs {af[ch], as[ch]} for ch=0..63 (dst gather)
// ABs[node][128]: pairs {bf[ch], bs[ch]} for ch=0..63 (src gather)
__device__ float g_ABd[NN * 128];
__device__ float g_ABs[NN * 128];
__device__ float g_h1[NN * DN];
__device__ float g_h2[NN * DN];

// ---------------------------------------------------------------------------
// Node projection, fused f+s: block computes BOTH Wf- and Ws- projections.
//   cb=0: {af,as} = h·{Wf,Ws}[0:64]   + {bf,bs}  -> ABd pairs
//   cb=1: {bf,bs} = h·{Wf,Ws}[64:128]            -> ABs pairs
// Stores are 2x STG.128 per node (pair layout native).
// ---------------------------------------------------------------------------
__global__ void __launch_bounds__(256) proj_kernel(
    const float* __restrict__ h, const float* __restrict__ Wf,
    const float* __restrict__ Ws, const float* __restrict__ bfv,
    const float* __restrict__ bsv, float* __restrict__ ABd,
    float* __restrict__ ABs)
{
    __shared__ float As[64][65];     // transposed: As[k][n]
    __shared__ float Bsq[64][128];   // Bsq[k][2j+m] = W_m[rowoff+k][j]

    const int tid = threadIdx.x;
    const int node0 = blockIdx.x * 64;
    const int cb = blockIdx.y;
    const int rowoff = cb ? 64 : 0;

#pragma unroll
    for (int t = 0; t < 32; t++) {
        int idx = t * 256 + tid;          // 8192 total
        int k = idx >> 7, col = idx & 127;
        int j = col >> 1, m = col & 1;
        const float* W = m ? Ws : Wf;
        Bsq[k][col] = W[(size_t)(rowoff + k) * 64 + j];
    }
#pragma unroll
    for (int t = 0; t < 16; t++) {
        int lin = t * 256 + tid;
        int n = lin >> 6, k = lin & 63;
        int node = node0 + n;
        As[k][n] = (node < NN) ? h[node * 64 + k] : 0.0f;
    }
    __syncthreads();

    const int tx = tid & 15;   // channel group: ch = 4tx .. 4tx+3
    const int ty = tid >> 4;   // node group: 4ty .. 4ty+3
    float2 acc[4][4];          // [node][ch] = {f-term, s-term}
#pragma unroll
    for (int i = 0; i < 4; i++)
#pragma unroll
        for (int j = 0; j < 4; j++) acc[i][j] = make_float2(0.f, 0.f);

#pragma unroll
    for (int k = 0; k < 64; k++) {
        float4 b01 = *(const float4*)&Bsq[k][8 * tx];
        float4 b23 = *(const float4*)&Bsq[k][8 * tx + 4];
#pragma unroll
        for (int i = 0; i < 4; i++) {
            float a = As[k][ty * 4 + i];
            acc[i][0].x += a * b01.x; acc[i][0].y += a * b01.y;
            acc[i][1].x += a * b01.z; acc[i][1].y += a * b01.w;
            acc[i][2].x += a * b23.x; acc[i][2].y += a * b23.y;
            acc[i][3].x += a * b23.z; acc[i][3].y += a * b23.w;
        }
    }

    float2 bias[4];
#pragma unroll
    for (int j = 0; j < 4; j++) bias[j] = make_float2(0.f, 0.f);
    if (cb == 0) {
#pragma unroll
        for (int j = 0; j < 4; j++)
            bias[j] = make_float2(bfv[tx * 4 + j], bsv[tx * 4 + j]);
    }

    float* outbase = cb ? ABs : ABd;
#pragma unroll
    for (int i = 0; i < 4; i++) {
        int node = node0 + ty * 4 + i;
        if (node < NN) {
            float4 o0 = make_float4(acc[i][0].x + bias[0].x, acc[i][0].y + bias[0].y,
                                    acc[i][1].x + bias[1].x, acc[i][1].y + bias[1].y);
            float4 o1 = make_float4(acc[i][2].x + bias[2].x, acc[i][2].y + bias[2].y,
                                    acc[i][3].x + bias[3].x, acc[i][3].y + bias[3].y);
            *(float4*)&outbase[(size_t)node * 128 + tx * 8] = o0;
            *(float4*)&outbase[(size_t)node * 128 + tx * 8 + 4] = o1;
        }
    }
}

// ---------------------------------------------------------------------------
// Edge GEMM kernel, edge-pair layout, 4 blocks/SM (64-reg cap).
// Thread (ch, eg) owns channel ch for 16 edges (8 edge-pairs).
// ---------------------------------------------------------------------------
__device__ __forceinline__ float sigmoidf_(float x) {
    return 1.0f / (1.0f + __expf(-x));
}
__device__ __forceinline__ float softplusf_(float x) {
    float ax = fabsf(x);
    float em = __expf(-ax);
    return fmaxf(x, 0.0f) + __logf(1.0f + em);
}

__global__ void __launch_bounds__(256, 4) edge_gemm_kernel(
    const int* __restrict__ ei, const float* __restrict__ ea,
    const float* __restrict__ ABd, const float* __restrict__ ABs,
    const float* __restrict__ Wf, const float* __restrict__ Ws,
    float* __restrict__ hout)
{
    __shared__ float Asd[32][64];    // [k][edge], non-duplicated (8 KB)
    __shared__ float Bq[32][128];    // [k][2ch + {f,s}] (16 KB)
    __shared__ int   ssrc[ET], sdst[ET];

    const int tid = threadIdx.x;
    const int e0 = blockIdx.x * ET;

    // --- Stage edge indices ---
    if (tid < ET) {
        ssrc[tid] = ei[e0 + tid];
        sdst[tid] = ei[NE + e0 + tid];
    }

    // --- Stage ea: thread t -> edge t&63, k-quarter t>>6 (bank = edge: CF) ---
    {
        const int e = tid & 63;
        const int k0 = (tid >> 6) * 8;
        const float* src = ea + (size_t)(e0 + e) * 32 + k0;
        float4 v0 = *(const float4*)(src);
        float4 v1 = *(const float4*)(src + 4);
#pragma unroll
        for (int j = 0; j < 4; j++) Asd[k0 + j][e] = (&v0.x)[j];
#pragma unroll
        for (int j = 0; j < 4; j++) Asd[k0 + 4 + j][e] = (&v1.x)[j];
    }

    // --- Stage paired bottom weights: Bq[k][2ch+m] = W_m[128+k][ch] ---
#pragma unroll
    for (int q = 0; q < 16; q++) {
        int idx = q * 256 + tid;           // 4096 total
        int k = idx >> 7, col = idx & 127;
        int ch = col >> 1, m = col & 1;
        const float* W = m ? Ws : Wf;
        Bq[k][col] = W[(size_t)(128 + k) * 64 + ch];
    }
    __syncthreads();

    const int ch = tid & 63;   // channel 0..63
    const int eg = tid >> 6;   // edge group: edges eg*16 .. +15

    const unsigned abase = (unsigned)__cvta_generic_to_shared(&Asd[0][eg * 16]);
    const unsigned bbase = (unsigned)__cvta_generic_to_shared(&Bq[0][ch * 2]);

    unsigned long long accf[8] = {0}, accs[8] = {0};

#pragma unroll
    for (int k = 0; k < 32; k++) {
        float wfv, wsv;
        asm volatile("ld.shared.v2.f32 {%0, %1}, [%2];"
                     : "=f"(wfv), "=f"(wsv) : "r"(bbase + k * 512u));
        unsigned long long wfp, wsp;
        asm("mov.b64 %0, {%1, %1};" : "=l"(wfp) : "f"(wfv));
        asm("mov.b64 %0, {%1, %1};" : "=l"(wsp) : "f"(wsv));

        unsigned long long ap[8];   // pairs {e0,e1}..{e14,e15}
        asm volatile("ld.shared.v2.b64 {%0, %1}, [%2];"
                     : "=l"(ap[0]), "=l"(ap[1]) : "r"(abase + k * 256u));
        asm volatile("ld.shared.v2.b64 {%0, %1}, [%2];"
                     : "=l"(ap[2]), "=l"(ap[3]) : "r"(abase + k * 256u + 16u));
        asm volatile("ld.shared.v2.b64 {%0, %1}, [%2];"
                     : "=l"(ap[4]), "=l"(ap[5]) : "r"(abase + k * 256u + 32u));
        asm volatile("ld.shared.v2.b64 {%0, %1}, [%2];"
                     : "=l"(ap[6]), "=l"(ap[7]) : "r"(abase + k * 256u + 48u));
#pragma unroll
        for (int p = 0; p < 8; p++) {
            asm("fma.rn.f32x2 %0, %1, %2, %3;"
                : "=l"(accf[p]) : "l"(ap[p]), "l"(wfp), "l"(accf[p]));
            asm("fma.rn.f32x2 %0, %1, %2, %3;"
                : "=l"(accs[p]) : "l"(ap[p]), "l"(wsp), "l"(accs[p]));
        }
    }

    // --- Epilogue: 4 waves of 4 edges (2 accumulator pairs each) ---
#pragma unroll
    for (int w = 0; w < 4; w++) {
        float2 dd[4], ss[4];
        int dsts[4];
#pragma unroll
        for (int i = 0; i < 4; i++) {
            int el = eg * 16 + w * 4 + i;
            dsts[i] = sdst[el];
            int sr = ssrc[el];
            dd[i] = *(const float2*)(ABd + (size_t)dsts[i] * 128 + ch * 2);
            ss[i] = *(const float2*)(ABs + (size_t)sr * 128 + ch * 2);
        }
#pragma unroll
        for (int p = 0; p < 2; p++) {
            int j = w * 2 + p;      // accumulator pair: edges {2j, 2j+1}
            float ef0, ef1, es0, es1;
            asm("mov.b64 {%0, %1}, %2;" : "=f"(ef0), "=f"(ef1) : "l"(accf[j]));
            asm("mov.b64 {%0, %1}, %2;" : "=f"(es0), "=f"(es1) : "l"(accs[j]));
#pragma unroll
            for (int b = 0; b < 2; b++) {
                int i = 2 * p + b;
                float ef = b ? ef1 : ef0;
                float es = b ? es1 : es0;
                float pf = dd[i].x + ss[i].x + ef;
                float qv = dd[i].y + ss[i].y + es;
                float m = sigmoidf_(pf) * softplusf_(qv);
                float* outp = hout + (size_t)dsts[i] * 64 + ch;
                asm volatile("red.global.add.f32 [%0], %1;"
                             :: "l"(outp), "f"(m) : "memory");
            }
        }
    }
}

// ---------------------------------------------------------------------------
__global__ void init_out_kernel(float* __restrict__ out, const float* __restrict__ b_out)
{
    int t = threadIdx.x;
    if (t < NG) out[t] = b_out[0];
}

__global__ void __launch_bounds__(256) pool_kernel(
    const float* __restrict__ h2, const int* __restrict__ batch,
    const float* __restrict__ Wout, float* __restrict__ out)
{
    const int warp = blockIdx.x * (blockDim.x >> 5) + (threadIdx.x >> 5);
    const int lane = threadIdx.x & 31;
    if (warp >= NN) return;
    float2 v = *(const float2*)(h2 + (size_t)warp * 64 + 2 * lane);
    float s = v.x * Wout[2 * lane] + v.y * Wout[2 * lane + 1];
#pragma unroll
    for (int off = 16; off; off >>= 1)
        s += __shfl_down_sync(0xffffffffu, s, off);
    if (lane == 0) atomicAdd(&out[batch[warp]], s);
}

// ---------------------------------------------------------------------------
extern "C" void kernel_launch(void* const* d_in, const int* in_sizes, int n_in,
                              void* d_out, int out_size)
{
    const float* x     = (const float*)d_in[0];
    const int*   ei    = (const int*)d_in[1];
    const float* ea    = (const float*)d_in[2];
    const int*   batch = (const int*)d_in[3];
    const float* Wf1  = (const float*)d_in[4];
    const float* bf1  = (const float*)d_in[5];
    const float* Ws1  = (const float*)d_in[6];
    const float* bs1  = (const float*)d_in[7];
    const float* Wf2  = (const float*)d_in[8];
    const float* bf2  = (const float*)d_in[9];
    const float* Ws2  = (const float*)d_in[10];
    const float* bs2  = (const float*)d_in[11];
    const float* Wout = (const float*)d_in[12];
    const float* bout = (const float*)d_in[13];
    float* out = (float*)d_out;

    float *ABd, *ABs, *h1, *h2;
    cudaGetSymbolAddress((void**)&ABd, g_ABd);
    cudaGetSymbolAddress((void**)&ABs, g_ABs);
    cudaGetSymbolAddress((void**)&h1, g_h1);
    cudaGetSymbolAddress((void**)&h2, g_h2);

    const dim3 pgrid((NN + 63) / 64, 2);
    const int egrid = NE / ET;   // 12500

    // ---- Layer 1 ----
    proj_kernel<<<pgrid, 256>>>(x, Wf1, Ws1, bf1, bs1, ABd, ABs);
    cudaMemcpyAsync(h1, x, (size_t)NN * DN * sizeof(float),
                    cudaMemcpyDeviceToDevice);
    edge_gemm_kernel<<<egrid, 256>>>(ei, ea, ABd, ABs, Wf1, Ws1, h1);

    // ---- Layer 2 ----
    proj_kernel<<<pgrid, 256>>>(h1, Wf2, Ws2, bf2, bs2, ABd, ABs);
    cudaMemcpyAsync(h2, h1, (size_t)NN * DN * sizeof(float),
                    cudaMemcpyDeviceToDevice);
    edge_gemm_kernel<<<egrid, 256>>>(ei, ea, ABd, ABs, Wf2, Ws2, h2);

    // ---- Pool + readout ----
    init_out_kernel<<<1, 512>>>(out, bout);
    pool_kernel<<<NN / 8, 256>>>(h2, batch, Wout, out);
}

// round 17
// speedup vs baseline: 1.0789x; 1.0486x over previous
#include <cuda_runtime.h>
#include <cuda_bf16.h>

#define NN 50000
#define NE 800000
#define NG 512
#define DN 64
#define DE 32
#define ET 64            // edges per block tile -> 12500 blocks

// Scratch (allocation-free: __device__ globals)
// ABd[node][128]: pairs {af[ch], as[ch]} for ch=0..63 (dst gather)
// ABs[node][128]: pairs {bf[ch], bs[ch]} for ch=0..63 (src gather)
__device__ float g_ABd[NN * 128];
__device__ float g_ABs[NN * 128];
__device__ float g_h1[NN * DN];
__device__ float g_h2[NN * DN];

// ---------------------------------------------------------------------------
// Node projection, fused f+s, pair-layout stores + self-term seed write.
//   cb=0: {af,as} = h·{Wf,Ws}[0:64]   + {bf,bs}  -> ABd pairs; hout = h (seed)
//   cb=1: {bf,bs} = h·{Wf,Ws}[64:128]            -> ABs pairs
// ---------------------------------------------------------------------------
__global__ void __launch_bounds__(256) proj_kernel(
    const float* __restrict__ h, const float* __restrict__ Wf,
    const float* __restrict__ Ws, const float* __restrict__ bfv,
    const float* __restrict__ bsv, float* __restrict__ ABd,
    float* __restrict__ ABs, float* __restrict__ hout)
{
    __shared__ float As[64][65];     // transposed: As[k][n]
    __shared__ float Bsq[64][128];   // Bsq[k][2j+m] = W_m[rowoff+k][j]

    const int tid = threadIdx.x;
    const int node0 = blockIdx.x * 64;
    const int cb = blockIdx.y;
    const int rowoff = cb ? 64 : 0;

#pragma unroll
    for (int t = 0; t < 32; t++) {
        int idx = t * 256 + tid;          // 8192 total
        int k = idx >> 7, col = idx & 127;
        int j = col >> 1, m = col & 1;
        const float* W = m ? Ws : Wf;
        Bsq[k][col] = W[(size_t)(rowoff + k) * 64 + j];
    }
#pragma unroll
    for (int t = 0; t < 16; t++) {
        int lin = t * 256 + tid;
        int n = lin >> 6, k = lin & 63;
        int node = node0 + n;
        As[k][n] = (node < NN) ? h[node * 64 + k] : 0.0f;
    }
    __syncthreads();

    const int tx = tid & 15;   // channel group: ch = 4tx .. 4tx+3
    const int ty = tid >> 4;   // node group: 4ty .. 4ty+3
    float2 acc[4][4];          // [node][ch] = {f-term, s-term}
#pragma unroll
    for (int i = 0; i < 4; i++)
#pragma unroll
        for (int j = 0; j < 4; j++) acc[i][j] = make_float2(0.f, 0.f);

#pragma unroll
    for (int k = 0; k < 64; k++) {
        float4 b01 = *(const float4*)&Bsq[k][8 * tx];
        float4 b23 = *(const float4*)&Bsq[k][8 * tx + 4];
#pragma unroll
        for (int i = 0; i < 4; i++) {
            float a = As[k][ty * 4 + i];
            acc[i][0].x += a * b01.x; acc[i][0].y += a * b01.y;
            acc[i][1].x += a * b01.z; acc[i][1].y += a * b01.w;
            acc[i][2].x += a * b23.x; acc[i][2].y += a * b23.y;
            acc[i][3].x += a * b23.z; acc[i][3].y += a * b23.w;
        }
    }

    float2 bias[4];
#pragma unroll
    for (int j = 0; j < 4; j++) bias[j] = make_float2(0.f, 0.f);
    if (cb == 0) {
#pragma unroll
        for (int j = 0; j < 4; j++)
            bias[j] = make_float2(bfv[tx * 4 + j], bsv[tx * 4 + j]);
    }

    float* outbase = cb ? ABs : ABd;
#pragma unroll
    for (int i = 0; i < 4; i++) {
        int node = node0 + ty * 4 + i;
        if (node < NN) {
            float4 o0 = make_float4(acc[i][0].x + bias[0].x, acc[i][0].y + bias[0].y,
                                    acc[i][1].x + bias[1].x, acc[i][1].y + bias[1].y);
            float4 o1 = make_float4(acc[i][2].x + bias[2].x, acc[i][2].y + bias[2].y,
                                    acc[i][3].x + bias[3].x, acc[i][3].y + bias[3].y);
            *(float4*)&outbase[(size_t)node * 128 + tx * 8] = o0;
            *(float4*)&outbase[(size_t)node * 128 + tx * 8 + 4] = o1;
        }
    }

    // Self-term seed: hout = h (replaces the D2D memcpy). cb==0 blocks only.
    if (cb == 0) {
#pragma unroll
        for (int i = 0; i < 4; i++) {
            int node = node0 + ty * 4 + i;
            if (node < NN) {
                float4 v = make_float4(As[tx * 4 + 0][ty * 4 + i],
                                       As[tx * 4 + 1][ty * 4 + i],
                                       As[tx * 4 + 2][ty * 4 + i],
                                       As[tx * 4 + 3][ty * 4 + i]);
                *(float4*)&hout[(size_t)node * 64 + tx * 4] = v;
            }
        }
    }
}

// ---------------------------------------------------------------------------
// Edge GEMM kernel, edge-pair layout, 4 blocks/SM (64-reg cap).
// Thread (ch, eg) owns channel ch for 16 edges (8 edge-pairs).
// ---------------------------------------------------------------------------
__device__ __forceinline__ float sigmoidf_(float x) {
    float th;
    asm("tanh.approx.f32 %0, %1;" : "=f"(th) : "f"(0.5f * x));
    return fmaf(0.5f, th, 0.5f);
}
__device__ __forceinline__ float softplusf_(float x) {
    float ax = fabsf(x);
    float em = __expf(-ax);
    return fmaxf(x, 0.0f) + __logf(1.0f + em);
}

__global__ void __launch_bounds__(256, 4) edge_gemm_kernel(
    const int* __restrict__ ei, const float* __restrict__ ea,
    const float* __restrict__ ABd, const float* __restrict__ ABs,
    const float* __restrict__ Wf, const float* __restrict__ Ws,
    float* __restrict__ hout)
{
    __shared__ float Asd[32][64];    // [k][edge], non-duplicated (8 KB)
    __shared__ float Bq[32][128];    // [k][2ch + {f,s}] (16 KB)
    __shared__ int   ssrc[ET], sdst[ET];

    const int tid = threadIdx.x;
    const int e0 = blockIdx.x * ET;

    // --- Stage edge indices ---
    if (tid < ET) {
        ssrc[tid] = ei[e0 + tid];
        sdst[tid] = ei[NE + e0 + tid];
    }

    // --- Stage ea: thread t -> edge t&63, k-quarter t>>6 (bank = edge: CF) ---
    {
        const int e = tid & 63;
        const int k0 = (tid >> 6) * 8;
        const float* src = ea + (size_t)(e0 + e) * 32 + k0;
        float4 v0 = *(const float4*)(src);
        float4 v1 = *(const float4*)(src + 4);
#pragma unroll
        for (int j = 0; j < 4; j++) Asd[k0 + j][e] = (&v0.x)[j];
#pragma unroll
        for (int j = 0; j < 4; j++) Asd[k0 + 4 + j][e] = (&v1.x)[j];
    }

    // --- Stage paired bottom weights: Bq[k][4u..4u+3] = {wf[2u],ws[2u],wf[2u+1],ws[2u+1]} ---
    {
        const int u = tid & 31;        // ch unit: channels {2u, 2u+1}
        const int k0 = tid >> 5;       // 0..7
#pragma unroll
        for (int it = 0; it < 4; it++) {
            int k = it * 8 + k0;
            float2 f2 = *(const float2*)(Wf + (size_t)(128 + k) * 64 + 2 * u);
            float2 s2 = *(const float2*)(Ws + (size_t)(128 + k) * 64 + 2 * u);
            float4 o = make_float4(f2.x, s2.x, f2.y, s2.y);
            *(float4*)&Bq[k][4 * u] = o;
        }
    }
    __syncthreads();

    const int ch = tid & 63;   // channel 0..63
    const int eg = tid >> 6;   // edge group: edges eg*16 .. +15

    const unsigned abase = (unsigned)__cvta_generic_to_shared(&Asd[0][eg * 16]);
    const unsigned bbase = (unsigned)__cvta_generic_to_shared(&Bq[0][ch * 2]);

    unsigned long long accf[8] = {0}, accs[8] = {0};

#pragma unroll
    for (int k = 0; k < 32; k++) {
        float wfv, wsv;
        asm volatile("ld.shared.v2.f32 {%0, %1}, [%2];"
                     : "=f"(wfv), "=f"(wsv) : "r"(bbase + k * 512u));
        unsigned long long wfp, wsp;
        asm("mov.b64 %0, {%1, %1};" : "=l"(wfp) : "f"(wfv));
        asm("mov.b64 %0, {%1, %1};" : "=l"(wsp) : "f"(wsv));

        unsigned long long ap[8];   // pairs {e0,e1}..{e14,e15}
        asm volatile("ld.shared.v2.b64 {%0, %1}, [%2];"
                     : "=l"(ap[0]), "=l"(ap[1]) : "r"(abase + k * 256u));
        asm volatile("ld.shared.v2.b64 {%0, %1}, [%2];"
                     : "=l"(ap[2]), "=l"(ap[3]) : "r"(abase + k * 256u + 16u));
        asm volatile("ld.shared.v2.b64 {%0, %1}, [%2];"
                     : "=l"(ap[4]), "=l"(ap[5]) : "r"(abase + k * 256u + 32u));
        asm volatile("ld.shared.v2.b64 {%0, %1}, [%2];"
                     : "=l"(ap[6]), "=l"(ap[7]) : "r"(abase + k * 256u + 48u));
#pragma unroll
        for (int p = 0; p < 8; p++) {
            asm("fma.rn.f32x2 %0, %1, %2, %3;"
                : "=l"(accf[p]) : "l"(ap[p]), "l"(wfp), "l"(accf[p]));
            asm("fma.rn.f32x2 %0, %1, %2, %3;"
                : "=l"(accs[p]) : "l"(ap[p]), "l"(wsp), "l"(accs[p]));
        }
    }

    // --- Epilogue: 4 waves of 4 edges (2 accumulator pairs each) ---
#pragma unroll
    for (int w = 0; w < 4; w++) {
        float2 dd[4], ss[4];
        int dsts[4];
#pragma unroll
        for (int i = 0; i < 4; i++) {
            int el = eg * 16 + w * 4 + i;
            dsts[i] = sdst[el];
            int sr = ssrc[el];
            dd[i] = *(const float2*)(ABd + (size_t)dsts[i] * 128 + ch * 2);
            ss[i] = *(const float2*)(ABs + (size_t)sr * 128 + ch * 2);
        }
#pragma unroll
        for (int p = 0; p < 2; p++) {
            int j = w * 2 + p;      // accumulator pair: edges {2j, 2j+1}
            float ef0, ef1, es0, es1;
            asm("mov.b64 {%0, %1}, %2;" : "=f"(ef0), "=f"(ef1) : "l"(accf[j]));
            asm("mov.b64 {%0, %1}, %2;" : "=f"(es0), "=f"(es1) : "l"(accs[j]));
#pragma unroll
            for (int b = 0; b < 2; b++) {
                int i = 2 * p + b;
                float ef = b ? ef1 : ef0;
                float es = b ? es1 : es0;
                float pf = dd[i].x + ss[i].x + ef;
                float qv = dd[i].y + ss[i].y + es;
                float m = sigmoidf_(pf) * softplusf_(qv);
                float* outp = hout + (size_t)dsts[i] * 64 + ch;
                asm volatile("red.global.add.f32 [%0], %1;"
                             :: "l"(outp), "f"(m) : "memory");
            }
        }
    }
}

// ---------------------------------------------------------------------------
__global__ void init_out_kernel(float* __restrict__ out, const float* __restrict__ b_out)
{
    int t = threadIdx.x;
    if (t < NG) out[t] = b_out[0];
}

__global__ void __launch_bounds__(256) pool_kernel(
    const float* __restrict__ h2, const int* __restrict__ batch,
    const float* __restrict__ Wout, float* __restrict__ out)
{
    const int warp = blockIdx.x * (blockDim.x >> 5) + (threadIdx.x >> 5);
    const int lane = threadIdx.x & 31;
    if (warp >= NN) return;
    float2 v = *(const float2*)(h2 + (size_t)warp * 64 + 2 * lane);
    float s = v.x * Wout[2 * lane] + v.y * Wout[2 * lane + 1];
#pragma unroll
    for (int off = 16; off; off >>= 1)
        s += __shfl_down_sync(0xffffffffu, s, off);
    if (lane == 0) atomicAdd(&out[batch[warp]], s);
}

// ---------------------------------------------------------------------------
extern "C" void kernel_launch(void* const* d_in, const int* in_sizes, int n_in,
                              void* d_out, int out_size)
{
    const float* x     = (const float*)d_in[0];
    const int*   ei    = (const int*)d_in[1];
    const float* ea    = (const float*)d_in[2];
    const int*   batch = (const int*)d_in[3];
    const float* Wf1  = (const float*)d_in[4];
    const float* bf1  = (const float*)d_in[5];
    const float* Ws1  = (const float*)d_in[6];
    const float* bs1  = (const float*)d_in[7];
    const float* Wf2  = (const float*)d_in[8];
    const float* bf2  = (const float*)d_in[9];
    const float* Ws2  = (const float*)d_in[10];
    const float* bs2  = (const float*)d_in[11];
    const float* Wout = (const float*)d_in[12];
    const float* bout = (const float*)d_in[13];
    float* out = (float*)d_out;

    float *ABd, *ABs, *h1, *h2;
    cudaGetSymbolAddress((void**)&ABd, g_ABd);
    cudaGetSymbolAddress((void**)&ABs, g_ABs);
    cudaGetSymbolAddress((void**)&h1, g_h1);
    cudaGetSymbolAddress((void**)&h2, g_h2);

    const dim3 pgrid((NN + 63) / 64, 2);
    const int egrid = NE / ET;   // 12500

    // ---- Layer 1 ----
    proj_kernel<<<pgrid, 256>>>(x, Wf1, Ws1, bf1, bs1, ABd, ABs, h1);
    edge_gemm_kernel<<<egrid, 256>>>(ei, ea, ABd, ABs, Wf1, Ws1, h1);

    // ---- Layer 2 ----
    proj_kernel<<<pgrid, 256>>>(h1, Wf2, Ws2, bf2, bs2, ABd, ABs, h2);
    edge_gemm_kernel<<<egrid, 256>>>(ei, ea, ABd, ABs, Wf2, Ws2, h2);

    // ---- Pool + readout ----
    init_out_kernel<<<1, 512>>>(out, bout);
    pool_kernel<<<NN / 8, 256>>>(h2, batch, Wout, out);
}